// round 7
// baseline (speedup 1.0000x reference)
#include <cuda_runtime.h>
#include <cstdint>

// Embedding gather with address-sorted access pattern.
// idx: [8192] int32, weight: [32000, 512] f32 (2 KB row), out: [8192, 512] f32
//
// K1 (1 CTA, 1024 thr): counting sort of tokens by weight-row bucket
//     (bucket = row >> 3, 4096 buckets). Emits packed (token<<17 | row).
// K2 (128 CTAs, 256 thr): CTA i gathers sorted tokens [64i, 64i+64) in two
//     batches of 32 rows, MLP=16 float4 loads per thread. Single resident
//     wave -> each CTA sweeps a narrow ascending address band of weight.

static constexpr int N_TOKENS   = 8192;
static constexpr int VEC_PER_ROW = 128;       // 512 f32 = 128 float4

// ---- sort kernel constants ----
static constexpr int SORT_THREADS = 1024;
static constexpr int N_BUCKETS    = 4096;     // 32000 rows >> 3 -> < 4096
static constexpr int TOK_PER_THR  = N_TOKENS / SORT_THREADS;   // 8

// ---- gather kernel constants ----
static constexpr int GB_CTAS     = 128;
static constexpr int GB_THREADS  = 256;
static constexpr int TOK_PER_CTA = N_TOKENS / GB_CTAS;         // 64
static constexpr int BATCH_TOK   = 32;
static constexpr int N_BATCH     = TOK_PER_CTA / BATCH_TOK;    // 2
static constexpr int VPT         = BATCH_TOK * VEC_PER_ROW / GB_THREADS; // 16

__device__ int g_sorted[N_TOKENS];   // packed: (token << 17) | row

__global__ void __launch_bounds__(SORT_THREADS, 1)
sort_tokens_kernel(const int* __restrict__ idx)
{
    __shared__ int cnt[N_BUCKETS];
    __shared__ int part[SORT_THREADS];

    const int t = threadIdx.x;

    // zero histogram
#pragma unroll
    for (int i = t; i < N_BUCKETS; i += SORT_THREADS) cnt[i] = 0;
    __syncthreads();

    // histogram (coalesced idx reads, kept in regs for scatter phase)
    int rows[TOK_PER_THR];
#pragma unroll
    for (int j = 0; j < TOK_PER_THR; j++) {
        rows[j] = idx[t + j * SORT_THREADS];
        atomicAdd(&cnt[rows[j] >> 3], 1);
    }
    __syncthreads();

    // exclusive scan over 4096: 4 per thread, then block scan of partials
    int local[4]; int s = 0;
#pragma unroll
    for (int j = 0; j < 4; j++) { local[j] = s; s += cnt[t * 4 + j]; }
    part[t] = s;
    __syncthreads();
    for (int off = 1; off < SORT_THREADS; off <<= 1) {
        int v = part[t];
        int u = (t >= off) ? part[t - off] : 0;
        __syncthreads();
        part[t] = v + u;
        __syncthreads();
    }
    const int base = (t == 0) ? 0 : part[t - 1];
    __syncthreads();
#pragma unroll
    for (int j = 0; j < 4; j++) cnt[t * 4 + j] = base + local[j];
    __syncthreads();

    // scatter packed (token, row) into sorted positions
#pragma unroll
    for (int j = 0; j < TOK_PER_THR; j++) {
        const int token = t + j * SORT_THREADS;
        const int r     = rows[j];
        const int pos   = atomicAdd(&cnt[r >> 3], 1);
        g_sorted[pos]   = (token << 17) | r;
    }
}

__global__ void __launch_bounds__(GB_THREADS)
banded_gather_kernel(const float4* __restrict__ weight,
                     float4* __restrict__ out)
{
    __shared__ int s_pair[BATCH_TOK];

    const int t    = threadIdx.x;
    const int base = blockIdx.x * TOK_PER_CTA;

#pragma unroll
    for (int b = 0; b < N_BATCH; b++) {
        if (t < BATCH_TOK)
            s_pair[t] = g_sorted[base + b * BATCH_TOK + t];
        __syncthreads();

        // Front-batched gathers: 16 independent LDG.128 per thread,
        // addresses ascending within this CTA's band.
        float4 v[VPT];
#pragma unroll
        for (int k = 0; k < VPT; k++) {
            const int j   = t + k * GB_THREADS;   // 0..4095
            const int tk  = j >> 7;               // token in batch
            const int c   = j & (VEC_PER_ROW - 1);
            const int row = s_pair[tk] & 0x1FFFF;
            v[k] = __ldg(&weight[(long long)row * VEC_PER_ROW + c]);
        }

#pragma unroll
        for (int k = 0; k < VPT; k++) {
            const int j     = t + k * GB_THREADS;
            const int tk    = j >> 7;
            const int c     = j & (VEC_PER_ROW - 1);
            const int token = s_pair[tk] >> 17;
            out[(long long)token * VEC_PER_ROW + c] = v[k];
        }
        __syncthreads();
    }
}

extern "C" void kernel_launch(void* const* d_in, const int* in_sizes, int n_in,
                              void* d_out, int out_size)
{
    const int*   idx    = (const int*)d_in[0];    // x: [4, 2048] int32
    const float* weight = (const float*)d_in[1];  // [32000, 512] f32
    float*       out    = (float*)d_out;          // [4, 2048, 512] f32

    sort_tokens_kernel<<<1, SORT_THREADS>>>(idx);
    banded_gather_kernel<<<GB_CTAS, GB_THREADS>>>(
        (const float4*)weight, (float4*)out);
}